// round 3
// baseline (speedup 1.0000x reference)
#include <cuda_runtime.h>
#include <cuda_bf16.h>

#define NX 192
#define NY 192
#define NZ 192
#define NXY (NX * NY)

#define BXD 32                 // lanes = x
#define WYD 4                  // warps per block, each owns YPT y-rows
#define YPT 4
#define ZCHUNK 12              // must be divisible by 3 (register rotation)
#define NTHREADS (BXD * WYD)   // 128
#define GXB (NX / BXD)         // 6
#define GYB (NY / (WYD * YPT)) // 12
#define GZB (NZ / ZCHUNK)      // 16
#define NBLOCKS (GXB * GYB * GZB) // 1152

__device__ double g_acc = 0.0;
__device__ unsigned int g_done = 0;

// Per-plane 2D stats for YPT output rows; x-neighbors via shuffle, y in regs:
//   gx = sum_{dy} [v(x+1)-v(x-1)]   (-> Ix after z triple-sum)
//   gy = rowsum(y+1) - rowsum(y-1)  (-> Iy after z triple-sum)
//   b  = 3x3 box sum                (-> Iz via b(z+1)-b(z-1))
__device__ __forceinline__ void plane_pass(
    const float* __restrict__ plane, const int* __restrict__ rowoff,
    int x, int xe, bool edge, int lane,
    float* __restrict__ gx, float* __restrict__ gy, float* __restrict__ b)
{
    float h[YPT + 2], d[YPT + 2];
#pragma unroll
    for (int r = 0; r < YPT + 2; ++r) {
        const float* row = plane + rowoff[r];
        float v  = row[x];
        float vm = __shfl_up_sync(0xFFFFFFFFu, v, 1);
        float vp = __shfl_down_sync(0xFFFFFFFFu, v, 1);
        float ve = 0.0f;
        if (edge) ve = row[xe];           // predicated LDG, lanes 0 & 31 only
        if (lane == 0)  vm = ve;
        if (lane == 31) vp = ve;
        h[r] = vm + v + vp;
        d[r] = vp - vm;
    }
#pragma unroll
    for (int i = 0; i < YPT; ++i) {
        gx[i] = d[i] + d[i + 1] + d[i + 2];
        gy[i] = h[i + 2] - h[i];
        b[i]  = h[i] + h[i + 1] + h[i + 2];
    }
}

__global__ __launch_bounds__(NTHREADS, 5)
void ngf_kernel(const float* __restrict__ I,
                const float* __restrict__ J,
                const float* __restrict__ M,
                float* __restrict__ out)
{
    __shared__ float warp_sums[WYD];

    const int lane = threadIdx.x;
    const int wy   = threadIdx.y;
    const int tid  = wy * BXD + lane;
    const int x    = blockIdx.x * BXD + lane;
    const int yb   = blockIdx.y * (WYD * YPT) + wy * YPT;
    const int z0   = blockIdx.z * ZCHUNK;

    // Clamped y row offsets, constant across z
    int rowoff[YPT + 2];
#pragma unroll
    for (int r = 0; r < YPT + 2; ++r) {
        int gy = yb - 1 + r;
        gy = gy < 0 ? 0 : (gy > NY - 1 ? NY - 1 : gy);
        rowoff[r] = gy * NX;
    }

    const bool edge = (lane == 0) || (lane == 31);
    int xe;
    {
        int xm = x - 1 < 0 ? 0 : x - 1;
        int xp = x + 1 > NX - 1 ? NX - 1 : x + 1;
        xe = (lane == 0) ? xm : xp;
    }

    // Rotating per-plane stats: slot s holds stats for one z-plane.
    float gxI[3][YPT], gyI[3][YPT], bI[3][YPT];
    float gxJ[3][YPT], gyJ[3][YPT], bJ[3][YPT];

    // Prologue: stats for planes z0-1 (clamped) -> slot 0, z0 -> slot 1
    {
        int gzm = z0 - 1 < 0 ? 0 : z0 - 1;
        const float* pI = I + (size_t)gzm * NXY;
        const float* pJ = J + (size_t)gzm * NXY;
        plane_pass(pI, rowoff, x, xe, edge, lane, gxI[0], gyI[0], bI[0]);
        plane_pass(pJ, rowoff, x, xe, edge, lane, gxJ[0], gyJ[0], bJ[0]);
        pI = I + (size_t)z0 * NXY;
        pJ = J + (size_t)z0 * NXY;
        plane_pass(pI, rowoff, x, xe, edge, lane, gxI[1], gyI[1], bI[1]);
        plane_pass(pJ, rowoff, x, xe, edge, lane, gxJ[1], gyJ[1], bJ[1]);
    }

    float acc = 0.0f;
    const float* mp = M + (size_t)z0 * NXY + x;   // mask plane ptr (incremented)

    for (int k = 0; k < ZCHUNK; k += 3) {
#pragma unroll
        for (int u = 0; u < 3; ++u) {
            // Output plane z = z0+k+u. Need stats(z+1) -> slot s2.
            const int s0 = u, s1 = (u + 1) % 3, s2 = (u + 2) % 3;
            int zq = z0 + k + u + 1;
            int gz = zq > NZ - 1 ? NZ - 1 : zq;   // top clamp only
            const float* pI = I + (size_t)gz * NXY;
            const float* pJ = J + (size_t)gz * NXY;
            plane_pass(pI, rowoff, x, xe, edge, lane, gxI[s2], gyI[s2], bI[s2]);
            plane_pass(pJ, rowoff, x, xe, edge, lane, gxJ[s2], gyJ[s2], bJ[s2]);

#pragma unroll
            for (int i = 0; i < YPT; ++i) {
                // Unscaled gradient sums (true gradient = 0.5 * these)
                float Ix = gxI[s0][i] + gxI[s1][i] + gxI[s2][i];
                float Iy = gyI[s0][i] + gyI[s1][i] + gyI[s2][i];
                float Iz = bI[s2][i] - bI[s0][i];
                float Jx = gxJ[s0][i] + gxJ[s1][i] + gxJ[s2][i];
                float Jy = gyJ[s0][i] + gyJ[s1][i] + gyJ[s2][i];
                float Jz = bJ[s2][i] - bJ[s0][i];

                float ssi  = fmaf(Ix, Ix, fmaf(Iy, Iy, Iz * Iz));
                float ssj  = fmaf(Jx, Jx, fmaf(Jy, Jy, Jz * Jz));
                float sdot = fmaf(Ix, Jx, fmaf(Iy, Jy, Iz * Jz));

                float imag = fmaf(0.25f, ssi, 0.01f);   // 0.25*ssi + EPS^2
                float jmag = fmaf(0.25f, ssj, 0.01f);
                float ngf  = __fdividef(0.0625f * sdot * sdot, imag * jmag);

                float m = mp[rowoff[i + 1]];            // rowoff[i+1]==(yb+i)*NX
                acc = fmaf(1.0f - ngf, m, acc);
            }
            mp += NXY;
        }
    }

    // Block reduction
#pragma unroll
    for (int off = 16; off > 0; off >>= 1)
        acc += __shfl_xor_sync(0xFFFFFFFFu, acc, off);
    if (lane == 0) warp_sums[wy] = acc;
    __syncthreads();

    if (tid == 0) {
        float v = warp_sums[0] + warp_sums[1] + warp_sums[2] + warp_sums[3];
        atomicAdd(&g_acc, (double)v);
        __threadfence();
        unsigned prev = atomicAdd(&g_done, 1u);
        if (prev == NBLOCKS - 1) {
            // All other blocks' g_acc adds are fenced before their g_done
            // increments, so an atomic read here sees the full sum.
            double tot = atomicAdd(&g_acc, 0.0);
            out[0] = (float)(tot * (1.0 / (double)((long long)NX * NY * NZ)));
            g_acc = 0.0;       // reset for next replay (deterministic)
            __threadfence();
            g_done = 0;
        }
    }
}

extern "C" void kernel_launch(void* const* d_in, const int* in_sizes, int n_in,
                              void* d_out, int out_size) {
    const float* I = (const float*)d_in[0];
    const float* J = (const float*)d_in[1];
    const float* M = (const float*)d_in[2];
    float* out = (float*)d_out;

    dim3 block(BXD, WYD, 1);
    dim3 grid(GXB, GYB, GZB);   // 6 x 12 x 16 = 1152 CTAs
    ngf_kernel<<<grid, block>>>(I, J, M, out);
}

// round 4
// speedup vs baseline: 1.2930x; 1.2930x over previous
#include <cuda_runtime.h>
#include <cuda_bf16.h>

#define NX 192
#define NY 192
#define NZ 192
#define NXY (NX * NY)

#define BXD 32                 // lanes = x
#define WYD 4                  // warps per block, each owns YPT y-rows
#define YPT 2
#define ROWS (YPT + 2)         // 4
#define ZCHUNK 32
#define NTHREADS (BXD * WYD)   // 128
#define GXB (NX / BXD)         // 6
#define GYB (NY / (WYD * YPT)) // 24
#define GZB (NZ / ZCHUNK)      // 6
#define NBLOCKS (GXB * GYB * GZB) // 864  (<= 148*6 = single wave)

__device__ double g_acc = 0.0;
__device__ unsigned int g_done = 0;

// Per-plane 2D stats for YPT output rows; x-neighbors via shuffle, y in regs:
//   gx = sum_{dy} [v(x+1)-v(x-1)]   (-> Ix after z triple-sum)
//   gy = rowsum(y+1) - rowsum(y-1)  (-> Iy after z triple-sum)
//   b  = 3x3 box sum                (-> Iz via b(z+1)-b(z-1))
__device__ __forceinline__ void plane_pass(
    const float* __restrict__ plane, const int* __restrict__ rowoff,
    int x, int xe, bool edge, int lane,
    float* __restrict__ gx, float* __restrict__ gy, float* __restrict__ b)
{
    float h[ROWS], d[ROWS];
#pragma unroll
    for (int r = 0; r < ROWS; ++r) {
        const float* row = plane + rowoff[r];
        float v  = row[x];
        float vm = __shfl_up_sync(0xFFFFFFFFu, v, 1);
        float vp = __shfl_down_sync(0xFFFFFFFFu, v, 1);
        float ve = 0.0f;
        if (edge) ve = row[xe];           // predicated LDG, lanes 0 & 31 only
        if (lane == 0)  vm = ve;
        if (lane == 31) vp = ve;
        h[r] = vm + v + vp;
        d[r] = vp - vm;
    }
#pragma unroll
    for (int i = 0; i < YPT; ++i) {
        gx[i] = d[i] + d[i + 1] + d[i + 2];
        gy[i] = h[i + 2] - h[i];
        b[i]  = h[i] + h[i + 1] + h[i + 2];
    }
}

// One z-step: consume slots s0,s1 and freshly computed slot s2 for output
// plane z = z0+k; produce stats for plane z0+k+1 into slot s2 first.
#define STEP(s0, s1, s2, kk)                                                  \
    {                                                                         \
        int zq = z0 + (kk) + 1;                                               \
        int gz = zq > NZ - 1 ? NZ - 1 : zq;                                   \
        const float* pI = I + (size_t)gz * NXY;                               \
        const float* pJ = J + (size_t)gz * NXY;                               \
        plane_pass(pI, rowoff, x, xe, edge, lane, gxI[s2], gyI[s2], bI[s2]);  \
        plane_pass(pJ, rowoff, x, xe, edge, lane, gxJ[s2], gyJ[s2], bJ[s2]);  \
        _Pragma("unroll")                                                     \
        for (int i = 0; i < YPT; ++i) {                                       \
            float Ix = gxI[s0][i] + gxI[s1][i] + gxI[s2][i];                  \
            float Iy = gyI[s0][i] + gyI[s1][i] + gyI[s2][i];                  \
            float Iz = bI[s2][i] - bI[s0][i];                                 \
            float Jx = gxJ[s0][i] + gxJ[s1][i] + gxJ[s2][i];                  \
            float Jy = gyJ[s0][i] + gyJ[s1][i] + gyJ[s2][i];                  \
            float Jz = bJ[s2][i] - bJ[s0][i];                                 \
            float ssi  = fmaf(Ix, Ix, fmaf(Iy, Iy, Iz * Iz));                 \
            float ssj  = fmaf(Jx, Jx, fmaf(Jy, Jy, Jz * Jz));                 \
            float sdot = fmaf(Ix, Jx, fmaf(Iy, Jy, Iz * Jz));                 \
            float imag = fmaf(0.25f, ssi, 0.01f);                             \
            float jmag = fmaf(0.25f, ssj, 0.01f);                             \
            float ngf  = __fdividef(0.0625f * sdot * sdot, imag * jmag);      \
            float m = mp[rowoff[i + 1]];                                      \
            acc = fmaf(1.0f - ngf, m, acc);                                   \
        }                                                                     \
        mp += NXY;                                                            \
    }

__global__ __launch_bounds__(NTHREADS, 6)
void ngf_kernel(const float* __restrict__ I,
                const float* __restrict__ J,
                const float* __restrict__ M,
                float* __restrict__ out)
{
    __shared__ float warp_sums[WYD];

    const int lane = threadIdx.x;
    const int wy   = threadIdx.y;
    const int tid  = wy * BXD + lane;
    const int x    = blockIdx.x * BXD + lane;
    const int yb   = blockIdx.y * (WYD * YPT) + wy * YPT;
    const int z0   = blockIdx.z * ZCHUNK;

    // Clamped y row offsets, constant across z
    int rowoff[ROWS];
#pragma unroll
    for (int r = 0; r < ROWS; ++r) {
        int gy = yb - 1 + r;
        gy = gy < 0 ? 0 : (gy > NY - 1 ? NY - 1 : gy);
        rowoff[r] = gy * NX;
    }

    const bool edge = (lane == 0) || (lane == 31);
    int xe;
    {
        int xm = x - 1 < 0 ? 0 : x - 1;
        int xp = x + 1 > NX - 1 ? NX - 1 : x + 1;
        xe = (lane == 0) ? xm : xp;
    }

    // Rotating per-plane stats (slot = one z-plane)
    float gxI[3][YPT], gyI[3][YPT], bI[3][YPT];
    float gxJ[3][YPT], gyJ[3][YPT], bJ[3][YPT];

    // Prologue: plane z0-1 (clamped) -> slot 0, plane z0 -> slot 1
    {
        int gzm = z0 - 1 < 0 ? 0 : z0 - 1;
        const float* pI = I + (size_t)gzm * NXY;
        const float* pJ = J + (size_t)gzm * NXY;
        plane_pass(pI, rowoff, x, xe, edge, lane, gxI[0], gyI[0], bI[0]);
        plane_pass(pJ, rowoff, x, xe, edge, lane, gxJ[0], gyJ[0], bJ[0]);
        pI = I + (size_t)z0 * NXY;
        pJ = J + (size_t)z0 * NXY;
        plane_pass(pI, rowoff, x, xe, edge, lane, gxI[1], gyI[1], bI[1]);
        plane_pass(pJ, rowoff, x, xe, edge, lane, gxJ[1], gyJ[1], bJ[1]);
    }

    float acc = 0.0f;
    const float* mp = M + (size_t)z0 * NXY + x;

    // 30 steps as 10 x 3-unrolled (static slot phase), then 2 peeled steps
    // (after a multiple of 3 steps the phase is back to 0).
    for (int kb = 0; kb < 30; kb += 3) {
        STEP(0, 1, 2, kb + 0)
        STEP(1, 2, 0, kb + 1)
        STEP(2, 0, 1, kb + 2)
    }
    STEP(0, 1, 2, 30)
    STEP(1, 2, 0, 31)

    // Block reduction
#pragma unroll
    for (int off = 16; off > 0; off >>= 1)
        acc += __shfl_xor_sync(0xFFFFFFFFu, acc, off);
    if (lane == 0) warp_sums[wy] = acc;
    __syncthreads();

    if (tid == 0) {
        float v = warp_sums[0] + warp_sums[1] + warp_sums[2] + warp_sums[3];
        atomicAdd(&g_acc, (double)v);
        __threadfence();
        unsigned prev = atomicAdd(&g_done, 1u);
        if (prev == NBLOCKS - 1) {
            // All other blocks' g_acc adds are fenced before their g_done
            // increments, so an atomic read here sees the full sum.
            double tot = atomicAdd(&g_acc, 0.0);
            out[0] = (float)(tot * (1.0 / (double)((long long)NX * NY * NZ)));
            g_acc = 0.0;       // reset for next replay (deterministic)
            __threadfence();
            g_done = 0;
        }
    }
}

extern "C" void kernel_launch(void* const* d_in, const int* in_sizes, int n_in,
                              void* d_out, int out_size) {
    const float* I = (const float*)d_in[0];
    const float* J = (const float*)d_in[1];
    const float* M = (const float*)d_in[2];
    float* out = (float*)d_out;

    dim3 block(BXD, WYD, 1);
    dim3 grid(GXB, GYB, GZB);   // 6 x 24 x 6 = 864 CTAs, single wave at 6/SM
    ngf_kernel<<<grid, block>>>(I, J, M, out);
}